// round 16
// baseline (speedup 1.0000x reference)
#include <cuda_runtime.h>
#include <cuda_bf16.h>
#include <math_constants.h>
#include <cstdint>

// Problem constants
#define N_TOK   32768      // B*S = 64*512
#define DIM     512
#define KCODES  1024
#define PAD_IDX 0
#define DECAY_F 0.99f
#define EPS_F   1e-5f
#define COMMIT_F 0.25f
#define MARGIN  0.06f      // candidate margin (~17 sigma of bf16 approx error)
#define CAP     32         // candidate capacity per token

// Output layout (float32 elements, tuple order concat)
#define OFF_Q    0
#define OFF_IDX  (N_TOK * DIM)
#define OFF_LOSS (OFF_IDX + N_TOK)
#define OFF_PERP (OFF_LOSS + 1)
#define OFF_CS   (OFF_PERP + 1)
#define OFF_EMAW (OFF_CS + KCODES)        // == 2 mod 4 -> float2 stores only
#define OFF_CB   (OFF_EMAW + KCODES*DIM)  // == 2 mod 4 -> float2 stores only

// Scratch (no allocations allowed -> __device__ globals)
__device__ unsigned char g_mask[N_TOK];
__device__ int   g_mask_mode;
__device__ int   g_idx[N_TOK];
__device__ float g_wsq[KCODES];
__device__ float g_xsq[N_TOK];
__device__ float g_dw[KCODES * DIM];
__device__ int   g_counts[KCODES];
__device__ float g_loss_sum;
__device__ int   g_nonpad;
__device__ __align__(16) __nv_bfloat16 g_xb[(size_t)N_TOK * DIM];   // 32 MB
__device__ __align__(16) __nv_bfloat16 g_wb[(size_t)KCODES * DIM];  // 1 MB
__device__ float g_tmin[(size_t)N_TOK * 8];   // per-token per-code-tile approx min
__device__ int   g_ncand[N_TOK];
__device__ float g_cand_s[(size_t)N_TOK * CAP];
__device__ int   g_cand_c[(size_t)N_TOK * CAP];

// ==================== PTX helpers (family-portable, no 'a' features) ====
__device__ __forceinline__ uint32_t smem_u32(const void* p) {
    uint32_t a;
    asm("{ .reg .u64 t; cvta.to.shared.u64 t, %1; cvt.u32.u64 %0, t; }"
        : "=r"(a) : "l"(p));
    return a;
}
__device__ __forceinline__ void ldmatrix_x4(uint32_t r[4], uint32_t addr) {
    asm volatile("ldmatrix.sync.aligned.m8n8.x4.shared.b16 {%0,%1,%2,%3}, [%4];"
        : "=r"(r[0]), "=r"(r[1]), "=r"(r[2]), "=r"(r[3]) : "r"(addr));
}
__device__ __forceinline__ void mma_bf16(float c[4], const uint32_t a[4],
                                         uint32_t b0, uint32_t b1) {
    asm volatile(
        "mma.sync.aligned.m16n8k16.row.col.f32.bf16.bf16.f32 "
        "{%0,%1,%2,%3}, {%4,%5,%6,%7}, {%8,%9}, {%0,%1,%2,%3};"
        : "+f"(c[0]), "+f"(c[1]), "+f"(c[2]), "+f"(c[3])
        : "r"(a[0]), "r"(a[1]), "r"(a[2]), "r"(a[3]), "r"(b0), "r"(b1));
}
__device__ __forceinline__ void cp16(uint32_t dst, const void* src) {
    asm volatile("cp.async.cg.shared.global [%0], [%1], 16;" :: "r"(dst), "l"(src));
}
#define CP_COMMIT() asm volatile("cp.async.commit_group;" ::: "memory")
#define CP_WAIT(n)  asm volatile("cp.async.wait_group %0;" :: "n"(n) : "memory")

// ---------------- kernel 0: zero scratch ----------------
__global__ void k_zero() {
    int t = blockIdx.x * blockDim.x + threadIdx.x;
    int stride = gridDim.x * blockDim.x;
    for (int i = t; i < KCODES * DIM; i += stride) g_dw[i] = 0.f;
    for (int i = t; i < N_TOK; i += stride) g_ncand[i] = 0;
    if (t < KCODES) g_counts[t] = 0;
    if (t == 0) { g_loss_sum = 0.f; g_nonpad = 0; }
}

// ---------------- detect padding_mask storage dtype ----------------
__global__ void k_detect(const unsigned char* __restrict__ m) {
    __shared__ int s_gt1, s_mod4;
    if (threadIdx.x == 0) { s_gt1 = 0; s_mod4 = 0; }
    __syncthreads();
    int gt1 = 0, mod4 = 0;
    for (int i = threadIdx.x; i < N_TOK; i += blockDim.x) {
        unsigned char b = m[i];
        if (b > 1) gt1 = 1;
        if (b && (i & 3)) mod4 = 1;
    }
    if (gt1)  atomicOr(&s_gt1, 1);
    if (mod4) atomicOr(&s_mod4, 1);
    __syncthreads();
    if (threadIdx.x == 0)
        g_mask_mode = s_gt1 ? 2 : (s_mod4 ? 0 : 1);
}

// ---------------- expand mask + count non-padded ----------------
__global__ void k_mask(const void* __restrict__ src) {
    int n = blockIdx.x * blockDim.x + threadIdx.x;
    int mode = g_mask_mode;
    unsigned char mv;
    if (mode == 0)      mv = (((const unsigned char*)src)[n] != 0);
    else if (mode == 1) mv = (((const int*)src)[n] != 0);
    else                mv = (((const float*)src)[n] != 0.f);
    g_mask[n] = mv;
    unsigned ball = __ballot_sync(0xffffffffu, mv == 0);
    if ((threadIdx.x & 31) == 0) atomicAdd(&g_nonpad, __popc(ball));
}

// ------- fused: sum of squares + bf16 convert (warp per row) -------
__device__ __forceinline__ float rowsq_cvt(const float4* row, __nv_bfloat16* dst,
                                           int lane) {
    float s = 0.f;
#pragma unroll
    for (int it = 0; it < 4; it++) {
        int i = lane + it * 32;
        float4 v = row[i];
        s += v.x * v.x + v.y * v.y + v.z * v.z + v.w * v.w;
        __nv_bfloat16 h[4] = {__float2bfloat16_rn(v.x), __float2bfloat16_rn(v.y),
                              __float2bfloat16_rn(v.z), __float2bfloat16_rn(v.w)};
        ((uint2*)dst)[i] = *(uint2*)h;
    }
#pragma unroll
    for (int o = 16; o > 0; o >>= 1) s += __shfl_xor_sync(0xffffffffu, s, o);
    return s;
}
__global__ void k_wsq(const float* __restrict__ W) {
    int k = blockIdx.x * 8 + (threadIdx.x >> 5);
    int lane = threadIdx.x & 31;
    float s = rowsq_cvt((const float4*)(W + (size_t)k * DIM),
                        g_wb + (size_t)k * DIM, lane);
    if (lane == 0) g_wsq[k] = s;
}
__global__ void k_xsq(const float* __restrict__ X) {
    int n = blockIdx.x * 8 + (threadIdx.x >> 5);
    int lane = threadIdx.x & 31;
    float s = rowsq_cvt((const float4*)(X + (size_t)n * DIM),
                        g_xb + (size_t)n * DIM, lane);
    if (lane == 0) g_xsq[n] = s;
}

// ---------------- pass A: bf16 HMMA GEMM + fused tile-argmin ----------------
// CTA tile: 128 tokens x 128 codes, D-chunks of 64, cp.async 3-stage pipeline.
// 8 warps = 4(m) x 2(n); warp tile 32x64; mma.m16n8k16.
// ONE __syncthreads per chunk: the barrier at iter top both releases the
// previous stage's readers and orders the prefetch issued later this iter.
#define NCHUNK (DIM / 64)   // 8
__global__ __launch_bounds__(256, 2) void k_gemm() {
    extern __shared__ __align__(16) unsigned char dyn[];   // 3 stages x 32KB
    __shared__ float s_xsq[128], s_wsq[128];
    __shared__ float s_rm[2][128];
    __shared__ float s_comb[128];

    const int tid = threadIdx.x;
    const int lane = tid & 31;
    const int wid = tid >> 5;
    const int warp_m = wid & 3;      // token group (32 rows)
    const int warp_n = wid >> 2;     // code group (64 cols)
    const int n0 = blockIdx.x * 128;
    const int c0 = blockIdx.y * 128;
    const uint32_t sb = smem_u32(dyn);

    if (tid < 128) { s_xsq[tid] = g_xsq[n0 + tid]; s_wsq[tid] = g_wsq[c0 + tid]; }

    float acc[2][8][4];
#pragma unroll
    for (int mt = 0; mt < 2; mt++)
#pragma unroll
        for (int nt = 0; nt < 8; nt++)
#pragma unroll
            for (int k = 0; k < 4; k++) acc[mt][nt][k] = 0.f;

    // ---- async tile loader: 2048 x 16B per chunk ----
    auto issue = [&](int chunk, int stage) {
        int d0 = chunk * 64;
        uint32_t base = sb + stage * 32768;
#pragma unroll
        for (int it = 0; it < 8; it++) {
            int i = tid + it * 256;            // 0..2047
            int isW = i >> 10;
            int r = i & 1023;
            int row = r >> 3, c16 = r & 7;
            const __nv_bfloat16* src =
                (isW ? g_wb + (size_t)(c0 + row) * DIM
                     : g_xb + (size_t)(n0 + row) * DIM) + d0 + c16 * 8;
            uint32_t off = (uint32_t)(row * 128 + c16 * 16);
            off ^= (off >> 3) & 0x70;          // Swizzle<3,4,3>
            cp16(base + isW * 16384 + off, src);
        }
    };

    issue(0, 0); CP_COMMIT();
    issue(1, 1); CP_COMMIT();

    for (int c = 0; c < NCHUNK; c++) {
        if (c < NCHUNK - 1) CP_WAIT(1); else CP_WAIT(0);
        __syncthreads();   // stage c ready; also: all readers of stage (c+2)%3 done
        const uint32_t bX = sb + (c % 3) * 32768;
        const uint32_t bW = bX + 16384;
#pragma unroll
        for (int ks = 0; ks < 4; ks++) {
            uint32_t a[2][4];
#pragma unroll
            for (int mt = 0; mt < 2; mt++) {
                int row = warp_m * 32 + mt * 16 + (lane & 15);
                int cb = ks * 32 + (lane >> 4) * 16;
                uint32_t off = (uint32_t)(row * 128 + cb);
                off ^= (off >> 3) & 0x70;
                ldmatrix_x4(a[mt], bX + off);
            }
            uint32_t b[4][4];
#pragma unroll
            for (int pp = 0; pp < 4; pp++) {
                int nrow = warp_n * 64 + pp * 16 + (lane & 7) + ((lane >> 4) << 3);
                int cb = ks * 32 + ((lane >> 3) & 1) * 16;
                uint32_t off = (uint32_t)(nrow * 128 + cb);
                off ^= (off >> 3) & 0x70;
                ldmatrix_x4(b[pp], bW + off);
            }
#pragma unroll
            for (int mt = 0; mt < 2; mt++)
#pragma unroll
                for (int nt = 0; nt < 8; nt++)
                    mma_bf16(acc[mt][nt], a[mt],
                             b[nt >> 1][(nt & 1) * 2], b[nt >> 1][(nt & 1) * 2 + 1]);
        }
        if (c + 2 < NCHUNK) { issue(c + 2, (c + 2) % 3); CP_COMMIT(); }
    }

    // ---- epilogue: per-row tile min over this CTA's 128 codes ----
    const int q = lane >> 2;              // quad row index
#pragma unroll
    for (int mt = 0; mt < 2; mt++) {
#pragma unroll
        for (int half = 0; half < 2; half++) {
            int r = warp_m * 32 + mt * 16 + q + half * 8;
            float xs = s_xsq[r];
            float m = CUDART_INF_F;
#pragma unroll
            for (int nt = 0; nt < 8; nt++) {
#pragma unroll
                for (int p = 0; p < 2; p++) {
                    int col = warp_n * 64 + nt * 8 + (lane & 3) * 2 + p;
                    float sc = (xs + s_wsq[col]) -
                               2.f * acc[mt][nt][half * 2 + p];
                    if (c0 + col == 0) sc = CUDART_INF_F;
                    m = fminf(m, sc);
                }
            }
            m = fminf(m, __shfl_xor_sync(0xffffffffu, m, 1));
            m = fminf(m, __shfl_xor_sync(0xffffffffu, m, 2));
            if ((lane & 3) == 0) s_rm[warp_n][r] = m;
        }
    }
    __syncthreads();
    if (tid < 128) {
        float comb = fminf(s_rm[0][tid], s_rm[1][tid]);
        s_comb[tid] = comb;
        g_tmin[(size_t)(n0 + tid) * 8 + blockIdx.y] = comb;
    }
    __syncthreads();

    // ---- candidate append: score <= tile_min + MARGIN ----
#pragma unroll
    for (int mt = 0; mt < 2; mt++) {
#pragma unroll
        for (int half = 0; half < 2; half++) {
            int r = warp_m * 32 + mt * 16 + q + half * 8;
            float xs = s_xsq[r];
            float thr = s_comb[r] + MARGIN;
#pragma unroll
            for (int nt = 0; nt < 8; nt++) {
#pragma unroll
                for (int p = 0; p < 2; p++) {
                    int col = warp_n * 64 + nt * 8 + (lane & 3) * 2 + p;
                    float sc = (xs + s_wsq[col]) -
                               2.f * acc[mt][nt][half * 2 + p];
                    int gcode = c0 + col;
                    if (gcode != 0 && sc <= thr) {
                        int n = n0 + r;
                        int pos = atomicAdd(&g_ncand[n], 1);
                        if (pos < CAP) {
                            g_cand_s[(size_t)n * CAP + pos] = sc;
                            g_cand_c[(size_t)n * CAP + pos] = gcode;
                        }
                    }
                }
            }
        }
    }
}

// ---------------- fused pass B: rescore + mask + quantize + loss + counts + dw ----
// Warp per token. One X-row load serves both the exact rescore and the
// straight-through quantize; dw accumulated with spread fp32 atomics (R13-proven).
__global__ __launch_bounds__(256) void k_final(const float* __restrict__ X,
                                               const float* __restrict__ W,
                                               float* __restrict__ out) {
    const int warp = threadIdx.x >> 5;
    const int lane = threadIdx.x & 31;
    const int n = blockIdx.x * 8 + warp;

    // global approx min over the 8 tile mins
    float tm = (lane < 8) ? g_tmin[(size_t)n * 8 + lane] : CUDART_INF_F;
#pragma unroll
    for (int o = 16; o > 0; o >>= 1)
        tm = fminf(tm, __shfl_xor_sync(0xffffffffu, tm, o));
    const float thr = tm + MARGIN;

    int nc = g_ncand[n];
    if (nc > CAP) nc = CAP;

    // X row, lane-partitioned: lane holds floats [lane*16, lane*16+16)
    float4 xv[4];
    const float4* xr = (const float4*)(X + (size_t)n * DIM + lane * 16);
#pragma unroll
    for (int qq = 0; qq < 4; qq++) xv[qq] = xr[qq];
    const float xsq = g_xsq[n];

    float bestv = CUDART_INF_F;
    int   besti = 0x7fffffff;
    for (int j = 0; j < nc; j++) {
        float s = g_cand_s[(size_t)n * CAP + j];
        if (s > thr) continue;
        int c = g_cand_c[(size_t)n * CAP + j];
        const float4* wr = (const float4*)(W + (size_t)c * DIM + lane * 16);
        float d = 0.f;
#pragma unroll
        for (int qq = 0; qq < 4; qq++) {
            float4 w4 = wr[qq];
            d = fmaf(xv[qq].x, w4.x, d);
            d = fmaf(xv[qq].y, w4.y, d);
            d = fmaf(xv[qq].z, w4.z, d);
            d = fmaf(xv[qq].w, w4.w, d);
        }
#pragma unroll
        for (int o = 16; o > 0; o >>= 1) d += __shfl_xor_sync(0xffffffffu, d, o);
        float se = (xsq + g_wsq[c]) - (d + d);
        if (se < bestv || (se == bestv && c < besti)) { bestv = se; besti = c; }
    }

    const int idxv = g_mask[n] ? PAD_IDX : besti;

    // quantize (straight-through), loss, dw — reusing xv
    const float4* wrow = (const float4*)(W + (size_t)idxv * DIM + lane * 16);
    float4*       qrow = (float4*)(out + (size_t)n * DIM + lane * 16);
    float*       dwrow = g_dw + (size_t)idxv * DIM + lane * 16;

    float ds = 0.f;
#pragma unroll
    for (int qq = 0; qq < 4; qq++) {
        float4 q = wrow[qq];
        float4 x = xv[qq];
        float dx0 = q.x - x.x, dx1 = q.y - x.y, dx2 = q.z - x.z, dx3 = q.w - x.w;
        float4 o;                                   // mimic x + (q - x) exactly
        o.x = x.x + dx0; o.y = x.y + dx1; o.z = x.z + dx2; o.w = x.w + dx3;
        qrow[qq] = o;
        ds += dx0 * dx0 + dx1 * dx1 + dx2 * dx2 + dx3 * dx3;
        atomicAdd(dwrow + qq * 4 + 0, x.x);
        atomicAdd(dwrow + qq * 4 + 1, x.y);
        atomicAdd(dwrow + qq * 4 + 2, x.z);
        atomicAdd(dwrow + qq * 4 + 3, x.w);
    }
#pragma unroll
    for (int o = 16; o > 0; o >>= 1) ds += __shfl_xor_sync(0xffffffffu, ds, o);

    __shared__ float sloss[8];
    if (lane == 0) {
        sloss[warp] = ds;
        atomicAdd(&g_counts[idxv], 1);
        out[OFF_IDX + n] = (float)idxv;
    }
    __syncthreads();
    if (threadIdx.x == 0) {
        float t = 0.f;
#pragma unroll
        for (int i = 0; i < 8; i++) t += sloss[i];
        atomicAdd(&g_loss_sum, t);
    }
}

// ---------------- cs / perplexity / loss scalars ----------------
__global__ void k_stats(const float* __restrict__ ema_cs, float* __restrict__ out) {
    int k = threadIdx.x;  // 1024 threads, 1 block
    float cnt = (float)g_counts[k];
    float cs0 = ema_cs[k] * DECAY_F + (1.f - DECAY_F) * cnt;
    float p = cnt / (float)N_TOK;
    float pl = p * logf(p + 1e-10f);

    __shared__ float s1[1024], s2[1024];
    s1[k] = cs0; s2[k] = pl;
    __syncthreads();
    for (int s = 512; s > 0; s >>= 1) {
        if (k < s) { s1[k] += s1[k + s]; s2[k] += s2[k + s]; }
        __syncthreads();
    }
    float nsum = s1[0];
    float csn = (cs0 + EPS_F) / (nsum + (float)KCODES * EPS_F) * nsum;
    out[OFF_CS + k] = csn;
    if (k == 0) {
        out[OFF_PERP] = expf(-s2[0]);
        float denom = (float)g_nonpad * (float)DIM;
        out[OFF_LOSS] = COMMIT_F * g_loss_sum / denom;
    }
}

// ---------------- EMA weight + codebook update ----------------
__global__ void k_update(const float* __restrict__ ema_w, float* __restrict__ out) {
    int t = blockIdx.x * blockDim.x + threadIdx.x;  // float2 index
    if (t >= KCODES * DIM / 2) return;
    int k = t / (DIM / 2);
    float csv = out[OFF_CS + k];
    float2 e = ((const float2*)ema_w)[t];
    float2 d = ((const float2*)g_dw)[t];
    float2 ne;
    ne.x = e.x * DECAY_F + (1.f - DECAY_F) * d.x;
    ne.y = e.y * DECAY_F + (1.f - DECAY_F) * d.y;
    *(float2*)(out + OFF_EMAW + (size_t)t * 2) = ne;
    float2 cb;
    if (k == PAD_IDX) { cb.x = 0.f; cb.y = 0.f; }
    else              { cb.x = ne.x / csv; cb.y = ne.y / csv; }
    *(float2*)(out + OFF_CB + (size_t)t * 2) = cb;
}

// ---------------- launch ----------------
#define GEMM_SMEM 98304   // 3 stages x (16KB X + 16KB W)

extern "C" void kernel_launch(void* const* d_in, const int* in_sizes, int n_in,
                              void* d_out, int out_size) {
    (void)in_sizes; (void)n_in; (void)out_size;
    const float* X   = (const float*)d_in[0];
    const void*  M   = d_in[1];
    const float* W   = (const float*)d_in[2];
    const float* ECS = (const float*)d_in[3];
    const float* EMA = (const float*)d_in[4];
    float* out = (float*)d_out;

    cudaFuncSetAttribute(k_gemm, cudaFuncAttributeMaxDynamicSharedMemorySize,
                         GEMM_SMEM);

    // k_gemm kept at global launch #6 for the ncu -s 5 -c 1 window.
    k_zero<<<512, 256>>>();
    k_wsq<<<KCODES / 8, 256>>>(W);
    k_xsq<<<N_TOK / 8, 256>>>(X);
    k_gemm<<<dim3(N_TOK / 128, KCODES / 128), 256, GEMM_SMEM>>>();
    k_detect<<<1, 256>>>((const unsigned char*)M);
    k_mask<<<N_TOK / 256, 256>>>(M);
    k_final<<<N_TOK / 8, 256>>>(X, W, out);
    k_stats<<<1, 1024>>>(ECS, out);
    k_update<<<(KCODES * DIM / 2 + 255) / 256, 256>>>(EMA, out);
}

// round 17
// speedup vs baseline: 1.4007x; 1.4007x over previous
#include <cuda_runtime.h>
#include <cuda_bf16.h>
#include <math_constants.h>
#include <cstdint>

// Problem constants
#define N_TOK   32768      // B*S = 64*512
#define DIM     512
#define KCODES  1024
#define PAD_IDX 0
#define DECAY_F 0.99f
#define EPS_F   1e-5f
#define COMMIT_F 0.25f
#define MARGIN  0.06f      // candidate margin (~17 sigma of bf16 approx error)
#define CAP     32         // candidate capacity per token

// Output layout (float32 elements, tuple order concat)
#define OFF_Q    0
#define OFF_IDX  (N_TOK * DIM)
#define OFF_LOSS (OFF_IDX + N_TOK)
#define OFF_PERP (OFF_LOSS + 1)
#define OFF_CS   (OFF_PERP + 1)
#define OFF_EMAW (OFF_CS + KCODES)        // == 2 mod 4 -> float2 stores only
#define OFF_CB   (OFF_EMAW + KCODES*DIM)  // == 2 mod 4 -> float2 stores only

// Scratch (no allocations allowed -> __device__ globals)
__device__ unsigned char g_mask[N_TOK];
__device__ int   g_gt1, g_mod4;
__device__ int   g_idx[N_TOK];
__device__ float g_wsq[KCODES];
__device__ float g_xsq[N_TOK];
__device__ float g_dw[KCODES * DIM];
__device__ int   g_counts[KCODES];
__device__ float g_loss_sum;
__device__ int   g_nonpad;
__device__ __align__(16) __nv_bfloat16 g_xb[(size_t)N_TOK * DIM];   // 32 MB
__device__ __align__(16) __nv_bfloat16 g_wb[(size_t)KCODES * DIM];  // 1 MB
__device__ float g_tmin[(size_t)N_TOK * 8];   // per-token per-code-tile approx min
__device__ int   g_ncand[N_TOK];
__device__ float g_cand_s[(size_t)N_TOK * CAP];
__device__ int   g_cand_c[(size_t)N_TOK * CAP];

// ==================== PTX helpers (family-portable, no 'a' features) ====
__device__ __forceinline__ uint32_t smem_u32(const void* p) {
    uint32_t a;
    asm("{ .reg .u64 t; cvta.to.shared.u64 t, %1; cvt.u32.u64 %0, t; }"
        : "=r"(a) : "l"(p));
    return a;
}
__device__ __forceinline__ void ldmatrix_x4(uint32_t r[4], uint32_t addr) {
    asm volatile("ldmatrix.sync.aligned.m8n8.x4.shared.b16 {%0,%1,%2,%3}, [%4];"
        : "=r"(r[0]), "=r"(r[1]), "=r"(r[2]), "=r"(r[3]) : "r"(addr));
}
__device__ __forceinline__ void mma_bf16(float c[4], const uint32_t a[4],
                                         uint32_t b0, uint32_t b1) {
    asm volatile(
        "mma.sync.aligned.m16n8k16.row.col.f32.bf16.bf16.f32 "
        "{%0,%1,%2,%3}, {%4,%5,%6,%7}, {%8,%9}, {%0,%1,%2,%3};"
        : "+f"(c[0]), "+f"(c[1]), "+f"(c[2]), "+f"(c[3])
        : "r"(a[0]), "r"(a[1]), "r"(a[2]), "r"(a[3]), "r"(b0), "r"(b1));
}
__device__ __forceinline__ void cp16(uint32_t dst, const void* src) {
    asm volatile("cp.async.cg.shared.global [%0], [%1], 16;" :: "r"(dst), "l"(src));
}
#define CP_COMMIT() asm volatile("cp.async.commit_group;" ::: "memory")
#define CP_WAIT(n)  asm volatile("cp.async.wait_group %0;" :: "n"(n) : "memory")

// ---------------- kernel 0: zero scratch ----------------
__global__ void k_zero() {
    int t = blockIdx.x * blockDim.x + threadIdx.x;
    int stride = gridDim.x * blockDim.x;
    for (int i = t; i < KCODES * DIM; i += stride) g_dw[i] = 0.f;
    for (int i = t; i < N_TOK; i += stride) g_ncand[i] = 0;
    if (t < KCODES) g_counts[t] = 0;
    if (t == 0) { g_loss_sum = 0.f; g_nonpad = 0; g_gt1 = 0; g_mod4 = 0; }
}

// ---------------- detect padding_mask storage dtype (parallel) ----------------
// Scans first N_TOK bytes: any byte>1 -> fp32; nonzero at off%4!=0 -> u8 bool;
// else int32.
__global__ void k_detect(const unsigned char* __restrict__ m) {
    int i = blockIdx.x * blockDim.x + threadIdx.x;
    unsigned char b = m[i];
    unsigned bal1 = __ballot_sync(0xffffffffu, b > 1);
    unsigned bal2 = __ballot_sync(0xffffffffu, b && (i & 3));
    if ((threadIdx.x & 31) == 0) {
        if (bal1) atomicOr(&g_gt1, 1);
        if (bal2) atomicOr(&g_mod4, 1);
    }
}

// ---------------- expand mask + count non-padded ----------------
__global__ void k_mask(const void* __restrict__ src) {
    int n = blockIdx.x * blockDim.x + threadIdx.x;
    int mode = g_gt1 ? 2 : (g_mod4 ? 0 : 1);
    unsigned char mv;
    if (mode == 0)      mv = (((const unsigned char*)src)[n] != 0);
    else if (mode == 1) mv = (((const int*)src)[n] != 0);
    else                mv = (((const float*)src)[n] != 0.f);
    g_mask[n] = mv;
    unsigned ball = __ballot_sync(0xffffffffu, mv == 0);
    if ((threadIdx.x & 31) == 0) atomicAdd(&g_nonpad, __popc(ball));
}

// ------- fused: sum of squares + bf16 convert (warp per row) -------
__device__ __forceinline__ float rowsq_cvt(const float4* row, __nv_bfloat16* dst,
                                           int lane) {
    float s = 0.f;
#pragma unroll
    for (int it = 0; it < 4; it++) {
        int i = lane + it * 32;
        float4 v = row[i];
        s += v.x * v.x + v.y * v.y + v.z * v.z + v.w * v.w;
        __nv_bfloat16 h[4] = {__float2bfloat16_rn(v.x), __float2bfloat16_rn(v.y),
                              __float2bfloat16_rn(v.z), __float2bfloat16_rn(v.w)};
        ((uint2*)dst)[i] = *(uint2*)h;
    }
#pragma unroll
    for (int o = 16; o > 0; o >>= 1) s += __shfl_xor_sync(0xffffffffu, s, o);
    return s;
}
__global__ void k_wsq(const float* __restrict__ W) {
    int k = blockIdx.x * 8 + (threadIdx.x >> 5);
    int lane = threadIdx.x & 31;
    float s = rowsq_cvt((const float4*)(W + (size_t)k * DIM),
                        g_wb + (size_t)k * DIM, lane);
    if (lane == 0) g_wsq[k] = s;
}
__global__ void k_xsq(const float* __restrict__ X) {
    int n = blockIdx.x * 8 + (threadIdx.x >> 5);
    int lane = threadIdx.x & 31;
    float s = rowsq_cvt((const float4*)(X + (size_t)n * DIM),
                        g_xb + (size_t)n * DIM, lane);
    if (lane == 0) g_xsq[n] = s;
}

// ---------------- pass A: bf16 HMMA GEMM + fused tile-argmin ----------------
// (exact R13 structure: 2-stage cp.async, 128x128 tile, 8 warps 4(m)x2(n))
__global__ __launch_bounds__(256, 2) void k_gemm() {
    extern __shared__ __align__(16) unsigned char dyn[];   // 2 stages x 32KB
    __shared__ float s_xsq[128], s_wsq[128];
    __shared__ float s_rm[2][128];
    __shared__ float s_comb[128];

    const int tid = threadIdx.x;
    const int lane = tid & 31;
    const int wid = tid >> 5;
    const int warp_m = wid & 3;      // token group (32 rows)
    const int warp_n = wid >> 2;     // code group (64 cols)
    const int n0 = blockIdx.x * 128;
    const int c0 = blockIdx.y * 128;
    const uint32_t sb = smem_u32(dyn);

    if (tid < 128) { s_xsq[tid] = g_xsq[n0 + tid]; s_wsq[tid] = g_wsq[c0 + tid]; }

    float acc[2][8][4];
#pragma unroll
    for (int mt = 0; mt < 2; mt++)
#pragma unroll
        for (int nt = 0; nt < 8; nt++)
#pragma unroll
            for (int k = 0; k < 4; k++) acc[mt][nt][k] = 0.f;

    auto issue = [&](int chunk, int stage) {
        int d0 = chunk * 64;
        uint32_t base = sb + stage * 32768;
#pragma unroll
        for (int it = 0; it < 8; it++) {
            int i = tid + it * 256;            // 0..2047
            int isW = i >> 10;
            int r = i & 1023;
            int row = r >> 3, c16 = r & 7;
            const __nv_bfloat16* src =
                (isW ? g_wb + (size_t)(c0 + row) * DIM
                     : g_xb + (size_t)(n0 + row) * DIM) + d0 + c16 * 8;
            uint32_t off = (uint32_t)(row * 128 + c16 * 16);
            off ^= (off >> 3) & 0x70;          // Swizzle<3,4,3>
            cp16(base + isW * 16384 + off, src);
        }
    };

    issue(0, 0);
    CP_COMMIT();

    for (int c = 0; c < DIM / 64; c++) {
        if (c < DIM / 64 - 1) { issue(c + 1, (c + 1) & 1); CP_COMMIT(); CP_WAIT(1); }
        else CP_WAIT(0);
        __syncthreads();
        const uint32_t bX = sb + (c & 1) * 32768;
        const uint32_t bW = bX + 16384;
#pragma unroll
        for (int ks = 0; ks < 4; ks++) {
            uint32_t a[2][4];
#pragma unroll
            for (int mt = 0; mt < 2; mt++) {
                int row = warp_m * 32 + mt * 16 + (lane & 15);
                int cb = ks * 32 + (lane >> 4) * 16;
                uint32_t off = (uint32_t)(row * 128 + cb);
                off ^= (off >> 3) & 0x70;
                ldmatrix_x4(a[mt], bX + off);
            }
            uint32_t b[4][4];
#pragma unroll
            for (int pp = 0; pp < 4; pp++) {
                int nrow = warp_n * 64 + pp * 16 + (lane & 7) + ((lane >> 4) << 3);
                int cb = ks * 32 + ((lane >> 3) & 1) * 16;
                uint32_t off = (uint32_t)(nrow * 128 + cb);
                off ^= (off >> 3) & 0x70;
                ldmatrix_x4(b[pp], bW + off);
            }
#pragma unroll
            for (int mt = 0; mt < 2; mt++)
#pragma unroll
                for (int nt = 0; nt < 8; nt++)
                    mma_bf16(acc[mt][nt], a[mt],
                             b[nt >> 1][(nt & 1) * 2], b[nt >> 1][(nt & 1) * 2 + 1]);
        }
        __syncthreads();   // all reads of this stage done before it is refilled
    }

    // ---- epilogue: per-row tile min over this CTA's 128 codes ----
    const int q = lane >> 2;              // quad row index
#pragma unroll
    for (int mt = 0; mt < 2; mt++) {
#pragma unroll
        for (int half = 0; half < 2; half++) {
            int r = warp_m * 32 + mt * 16 + q + half * 8;
            float xs = s_xsq[r];
            float m = CUDART_INF_F;
#pragma unroll
            for (int nt = 0; nt < 8; nt++) {
#pragma unroll
                for (int p = 0; p < 2; p++) {
                    int col = warp_n * 64 + nt * 8 + (lane & 3) * 2 + p;
                    float sc = (xs + s_wsq[col]) -
                               2.f * acc[mt][nt][half * 2 + p];
                    if (c0 + col == 0) sc = CUDART_INF_F;
                    m = fminf(m, sc);
                }
            }
            m = fminf(m, __shfl_xor_sync(0xffffffffu, m, 1));
            m = fminf(m, __shfl_xor_sync(0xffffffffu, m, 2));
            if ((lane & 3) == 0) s_rm[warp_n][r] = m;
        }
    }
    __syncthreads();
    if (tid < 128) {
        float comb = fminf(s_rm[0][tid], s_rm[1][tid]);
        s_comb[tid] = comb;
        g_tmin[(size_t)(n0 + tid) * 8 + blockIdx.y] = comb;
    }
    __syncthreads();

    // ---- candidate append: score <= tile_min + MARGIN ----
#pragma unroll
    for (int mt = 0; mt < 2; mt++) {
#pragma unroll
        for (int half = 0; half < 2; half++) {
            int r = warp_m * 32 + mt * 16 + q + half * 8;
            float xs = s_xsq[r];
            float thr = s_comb[r] + MARGIN;
#pragma unroll
            for (int nt = 0; nt < 8; nt++) {
#pragma unroll
                for (int p = 0; p < 2; p++) {
                    int col = warp_n * 64 + nt * 8 + (lane & 3) * 2 + p;
                    float sc = (xs + s_wsq[col]) -
                               2.f * acc[mt][nt][half * 2 + p];
                    int gcode = c0 + col;
                    if (gcode != 0 && sc <= thr) {
                        int n = n0 + r;
                        int pos = atomicAdd(&g_ncand[n], 1);
                        if (pos < CAP) {
                            g_cand_s[(size_t)n * CAP + pos] = sc;
                            g_cand_c[(size_t)n * CAP + pos] = gcode;
                        }
                    }
                }
            }
        }
    }
}

// ---------------- pass B: global-min filter + exact fp32 rescore ----------------
// Warp per token; fully coalesced lane+it*32 partitioning (dot is invariant
// to lane partitioning of the D axis).
__global__ __launch_bounds__(256) void k_select2(const float* __restrict__ X,
                                                 const float* __restrict__ W) {
    const int warp = threadIdx.x >> 5;
    const int lane = threadIdx.x & 31;
    const int n = blockIdx.x * 8 + warp;

    float tm = (lane < 8) ? g_tmin[(size_t)n * 8 + lane] : CUDART_INF_F;
#pragma unroll
    for (int o = 16; o > 0; o >>= 1)
        tm = fminf(tm, __shfl_xor_sync(0xffffffffu, tm, o));
    const float thr = tm + MARGIN;

    int nc = g_ncand[n];
    if (nc > CAP) nc = CAP;

    float4 xv[4];
    const float4* xr = (const float4*)(X + (size_t)n * DIM);
#pragma unroll
    for (int qq = 0; qq < 4; qq++) xv[qq] = xr[lane + qq * 32];
    const float xsq = g_xsq[n];

    float bestv = CUDART_INF_F;
    int   besti = 0x7fffffff;
    for (int j = 0; j < nc; j++) {
        float s = g_cand_s[(size_t)n * CAP + j];
        if (s > thr) continue;
        int c = g_cand_c[(size_t)n * CAP + j];
        const float4* wr = (const float4*)(W + (size_t)c * DIM);
        float d = 0.f;
#pragma unroll
        for (int qq = 0; qq < 4; qq++) {
            float4 w4 = wr[lane + qq * 32];
            d = fmaf(xv[qq].x, w4.x, d);
            d = fmaf(xv[qq].y, w4.y, d);
            d = fmaf(xv[qq].z, w4.z, d);
            d = fmaf(xv[qq].w, w4.w, d);
        }
#pragma unroll
        for (int o = 16; o > 0; o >>= 1) d += __shfl_xor_sync(0xffffffffu, d, o);
        float se = (xsq + g_wsq[c]) - (d + d);
        if (se < bestv || (se == bestv && c < besti)) { bestv = se; besti = c; }
    }
    if (lane == 0) g_idx[n] = besti;
}

// ---------------- gather/quantize + loss + counts + dw (coalesced) ----------------
__global__ void k_epilogue(const float* __restrict__ X, const float* __restrict__ W,
                           float* __restrict__ out) {
    int warp = threadIdx.x >> 5;
    int lane = threadIdx.x & 31;
    int n = blockIdx.x * 8 + warp;

    int idxv = g_mask[n] ? PAD_IDX : g_idx[n];

    const float4* wrow = (const float4*)(W + (size_t)idxv * DIM);
    const float4* xrow = (const float4*)(X + (size_t)n * DIM);
    float4*       qrow = (float4*)(out + (size_t)n * DIM);
    float*       dwrow = g_dw + (size_t)idxv * DIM;

    float ds = 0.f;
#pragma unroll
    for (int it = 0; it < 4; it++) {
        int f4 = lane + it * 32;
        float4 q = wrow[f4];
        float4 x = xrow[f4];
        float dx0 = q.x - x.x, dx1 = q.y - x.y, dx2 = q.z - x.z, dx3 = q.w - x.w;
        float4 o;
        o.x = x.x + dx0; o.y = x.y + dx1; o.z = x.z + dx2; o.w = x.w + dx3;
        qrow[f4] = o;
        ds += dx0 * dx0 + dx1 * dx1 + dx2 * dx2 + dx3 * dx3;
        atomicAdd(&dwrow[f4 * 4 + 0], x.x);
        atomicAdd(&dwrow[f4 * 4 + 1], x.y);
        atomicAdd(&dwrow[f4 * 4 + 2], x.z);
        atomicAdd(&dwrow[f4 * 4 + 3], x.w);
    }
    for (int o = 16; o > 0; o >>= 1) ds += __shfl_xor_sync(0xffffffffu, ds, o);

    __shared__ float sloss[8];
    if (lane == 0) {
        sloss[warp] = ds;
        atomicAdd(&g_counts[idxv], 1);
        out[OFF_IDX + n] = (float)idxv;
    }
    __syncthreads();
    if (threadIdx.x == 0) {
        float t = 0.f;
#pragma unroll
        for (int i = 0; i < 8; i++) t += sloss[i];
        atomicAdd(&g_loss_sum, t);
    }
}

// ---------------- cs / perplexity / loss scalars ----------------
__global__ void k_stats(const float* __restrict__ ema_cs, float* __restrict__ out) {
    int k = threadIdx.x;  // 1024 threads, 1 block
    float cnt = (float)g_counts[k];
    float cs0 = ema_cs[k] * DECAY_F + (1.f - DECAY_F) * cnt;
    float p = cnt / (float)N_TOK;
    float pl = p * logf(p + 1e-10f);

    __shared__ float s1[1024], s2[1024];
    s1[k] = cs0; s2[k] = pl;
    __syncthreads();
    for (int s = 512; s > 0; s >>= 1) {
        if (k < s) { s1[k] += s1[k + s]; s2[k] += s2[k + s]; }
        __syncthreads();
    }
    float nsum = s1[0];
    float csn = (cs0 + EPS_F) / (nsum + (float)KCODES * EPS_F) * nsum;
    out[OFF_CS + k] = csn;
    if (k == 0) {
        out[OFF_PERP] = expf(-s2[0]);
        float denom = (float)g_nonpad * (float)DIM;
        out[OFF_LOSS] = COMMIT_F * g_loss_sum / denom;
    }
}

// ---------------- EMA weight + codebook update ----------------
__global__ void k_update(const float* __restrict__ ema_w, float* __restrict__ out) {
    int t = blockIdx.x * blockDim.x + threadIdx.x;  // float2 index
    if (t >= KCODES * DIM / 2) return;
    int k = t / (DIM / 2);
    float csv = out[OFF_CS + k];
    float2 e = ((const float2*)ema_w)[t];
    float2 d = ((const float2*)g_dw)[t];
    float2 ne;
    ne.x = e.x * DECAY_F + (1.f - DECAY_F) * d.x;
    ne.y = e.y * DECAY_F + (1.f - DECAY_F) * d.y;
    *(float2*)(out + OFF_EMAW + (size_t)t * 2) = ne;
    float2 cb;
    if (k == PAD_IDX) { cb.x = 0.f; cb.y = 0.f; }
    else              { cb.x = ne.x / csv; cb.y = ne.y / csv; }
    *(float2*)(out + OFF_CB + (size_t)t * 2) = cb;
}

// ---------------- launch ----------------
#define GEMM_SMEM 65536   // 2 stages x (16KB X + 16KB W)

extern "C" void kernel_launch(void* const* d_in, const int* in_sizes, int n_in,
                              void* d_out, int out_size) {
    (void)in_sizes; (void)n_in; (void)out_size;
    const float* X   = (const float*)d_in[0];
    const void*  M   = d_in[1];
    const float* W   = (const float*)d_in[2];
    const float* ECS = (const float*)d_in[3];
    const float* EMA = (const float*)d_in[4];
    float* out = (float*)d_out;

    cudaFuncSetAttribute(k_gemm, cudaFuncAttributeMaxDynamicSharedMemorySize,
                         GEMM_SMEM);

    // k_gemm kept at global launch #6 for the ncu -s 5 -c 1 window.
    k_zero<<<512, 256>>>();
    k_wsq<<<KCODES / 8, 256>>>(W);
    k_xsq<<<N_TOK / 8, 256>>>(X);
    k_gemm<<<dim3(N_TOK / 128, KCODES / 128), 256, GEMM_SMEM>>>();
    k_detect<<<N_TOK / 256, 256>>>((const unsigned char*)M);
    k_mask<<<N_TOK / 256, 256>>>(M);
    k_select2<<<N_TOK / 8, 256>>>(X, W);
    k_epilogue<<<N_TOK / 8, 256>>>(X, W, out);
    k_stats<<<1, 1024>>>(ECS, out);
    k_update<<<(KCODES * DIM / 2 + 255) / 256, 256>>>(EMA, out);
}